// round 1
// baseline (speedup 1.0000x reference)
#include <cuda_runtime.h>
#include <cuda_bf16.h>

// Fused BN(affine) -> ReLU -> 2x2 AvgPool(stride 2) -> 1x1 Conv (channel GEMM)
// x:           [N=32, C_in=32, H=256, W=256] f32
// conv_weight: [C_in=32, C_out=16] f32 (row-major, w[c*16+d])
// bn_scale/bn_bias: [32] f32
// out:         [N=32, C_out=16, 128, 128] f32
//
// Strategy: pure HBM-bound single pass. Each thread computes 2 adjacent pooled
// pixels (one float4 per input row per channel -> LDG.128, fully coalesced),
// accumulates the 32x16 channel GEMM in 32 registers, writes 16 float2 stores.

#define C_IN  32
#define C_OUT 16
#define HIN   256
#define WIN   256
#define POUT  128  // pooled H and W

__global__ __launch_bounds__(256) void fused_bn_relu_pool_conv(
    const float* __restrict__ x,
    const float* __restrict__ wmat,
    const float* __restrict__ scale,
    const float* __restrict__ bias,
    float* __restrict__ out)
{
    __shared__ float s_w[C_IN * C_OUT];
    __shared__ float s_sc[C_IN];
    __shared__ float s_bi[C_IN];

    const int tid = threadIdx.x;
    for (int i = tid; i < C_IN * C_OUT; i += 256) s_w[i] = wmat[i];
    if (tid < C_IN) { s_sc[tid] = scale[tid]; s_bi[tid] = bias[tid]; }
    __syncthreads();

    // Each thread: image n, pooled row h2, pooled columns {2*wq, 2*wq+1}.
    const int g   = blockIdx.x * 256 + tid;
    const int n   = g >> 13;          // 128*64 = 8192 thread-slots per image
    const int rem = g & 8191;
    const int h2  = rem >> 6;         // 0..127
    const int wq  = rem & 63;         // 0..63 (pair of pooled columns)

    // Input base: channel 0, row 2*h2, column 4*wq (16B aligned -> float4 OK)
    const float* base = x + ((size_t)n * C_IN * HIN + 2 * h2) * WIN + 4 * wq;

    float acc0[C_OUT], acc1[C_OUT];
#pragma unroll
    for (int d = 0; d < C_OUT; d++) { acc0[d] = 0.0f; acc1[d] = 0.0f; }

#pragma unroll
    for (int c = 0; c < C_IN; c++) {
        const float4 r0 = *reinterpret_cast<const float4*>(base + (size_t)c * (HIN * WIN));
        const float4 r1 = *reinterpret_cast<const float4*>(base + (size_t)c * (HIN * WIN) + WIN);
        const float sc = s_sc[c];
        const float bi = s_bi[c];

        // BN + ReLU on all 8 taps
        const float v0 = fmaxf(fmaf(r0.x, sc, bi), 0.0f);
        const float v1 = fmaxf(fmaf(r0.y, sc, bi), 0.0f);
        const float v2 = fmaxf(fmaf(r0.z, sc, bi), 0.0f);
        const float v3 = fmaxf(fmaf(r0.w, sc, bi), 0.0f);
        const float u0 = fmaxf(fmaf(r1.x, sc, bi), 0.0f);
        const float u1 = fmaxf(fmaf(r1.y, sc, bi), 0.0f);
        const float u2 = fmaxf(fmaf(r1.z, sc, bi), 0.0f);
        const float u3 = fmaxf(fmaf(r1.w, sc, bi), 0.0f);

        // 2x2 average pool -> two pooled values for this channel
        const float p0 = (v0 + v1 + u0 + u1) * 0.25f;
        const float p1 = (v2 + v3 + u2 + u3) * 0.25f;

        // Channel GEMM accumulate: acc[d] += p * W[c][d]
#pragma unroll
        for (int d = 0; d < C_OUT; d++) {
            const float w = s_w[c * C_OUT + d];
            acc0[d] = fmaf(p0, w, acc0[d]);
            acc1[d] = fmaf(p1, w, acc1[d]);
        }
    }

    // Output: out[n][d][h2][2*wq .. 2*wq+1], float2 per plane (8B aligned)
    float* o = out + (size_t)n * C_OUT * (POUT * POUT) + h2 * POUT + 2 * wq;
#pragma unroll
    for (int d = 0; d < C_OUT; d++) {
        *reinterpret_cast<float2*>(o + (size_t)d * (POUT * POUT)) =
            make_float2(acc0[d], acc1[d]);
    }
}

extern "C" void kernel_launch(void* const* d_in, const int* in_sizes, int n_in,
                              void* d_out, int out_size)
{
    const float* x     = (const float*)d_in[0];
    const float* wmat  = (const float*)d_in[1];
    const float* scale = (const float*)d_in[2];
    const float* bias  = (const float*)d_in[3];
    float* out         = (float*)d_out;

    // 32 images * 128 pooled rows * 64 column-pairs = 262144 threads
    fused_bn_relu_pool_conv<<<1024, 256>>>(x, wmat, scale, bias, out);
}

// round 2
// speedup vs baseline: 1.0589x; 1.0589x over previous
#include <cuda_runtime.h>
#include <cuda_bf16.h>

// Fused BN(affine) -> ReLU -> 2x2 AvgPool(stride 2) -> 1x1 Conv (channel GEMM)
// x:           [N=32, C_in=32, H=256, W=256] f32
// conv_weight: [C_in=32, C_out=16] f32 (row-major, w[c*16+d])
// bn_scale/bn_bias: [32] f32
// out:         [N=32, C_out=16, 128, 128] f32
//
// R2: raise occupancy (launch_bounds 256,4 -> <=64 regs, 32 warps/SM) and cut
// issue-slot count: packed f32x2 GEMM accumulators (16 FFMA2 vs 32 FFMA per
// channel), packed pre-scaled weights in shared (16 LDS.64 broadcasts vs 32
// LDS.32, pool *0.25 folded into weights). Accumulator b64 (lo,hi) == the
// float2 store, so the epilogue is a straight reinterpret.

#define C_IN  32
#define C_OUT 16
#define HIN   256
#define WIN   256
#define POUT  128  // pooled H and W

__device__ __forceinline__ unsigned long long pack_f32x2(float lo, float hi) {
    unsigned long long r;
    asm("mov.b64 %0, {%1, %2};" : "=l"(r) : "f"(lo), "f"(hi));
    return r;
}

__device__ __forceinline__ void fma_f32x2(unsigned long long& acc,
                                          unsigned long long a,
                                          unsigned long long b) {
    asm("fma.rn.f32x2 %0, %1, %2, %0;" : "+l"(acc) : "l"(a), "l"(b));
}

__global__ __launch_bounds__(256, 4) void fused_bn_relu_pool_conv(
    const float* __restrict__ x,
    const float* __restrict__ wmat,
    const float* __restrict__ scale,
    const float* __restrict__ bias,
    float* __restrict__ out)
{
    // Packed weights {0.25*w, 0.25*w} per (c,d): 32*16 float2 = 4 KB
    __shared__ float2 s_w2[C_IN * C_OUT];
    __shared__ float  s_sc[C_IN];
    __shared__ float  s_bi[C_IN];

    const int tid = threadIdx.x;
    for (int i = tid; i < C_IN * C_OUT; i += 256) {
        const float w = 0.25f * wmat[i];
        s_w2[i] = make_float2(w, w);
    }
    if (tid < C_IN) { s_sc[tid] = scale[tid]; s_bi[tid] = bias[tid]; }
    __syncthreads();

    // Each thread: image n, pooled row h2, pooled columns {2*wq, 2*wq+1}.
    const int g   = blockIdx.x * 256 + tid;
    const int n   = g >> 13;          // 128*64 = 8192 thread-slots per image
    const int rem = g & 8191;
    const int h2  = rem >> 6;         // 0..127
    const int wq  = rem & 63;         // 0..63 (pair of pooled columns)

    // Input base: channel 0, row 2*h2, column 4*wq (16B aligned -> float4 OK)
    const float* base = x + ((size_t)n * C_IN * HIN + 2 * h2) * WIN + 4 * wq;

    // 16 packed accumulators: lo half = pooled pixel 0, hi half = pixel 1
    unsigned long long acc[C_OUT];
#pragma unroll
    for (int d = 0; d < C_OUT; d++) acc[d] = 0ULL;

#pragma unroll
    for (int c = 0; c < C_IN; c++) {
        const float4 r0 = *reinterpret_cast<const float4*>(base + (size_t)c * (HIN * WIN));
        const float4 r1 = *reinterpret_cast<const float4*>(base + (size_t)c * (HIN * WIN) + WIN);
        const float sc = s_sc[c];
        const float bi = s_bi[c];

        // BN + ReLU on all 8 taps
        const float v0 = fmaxf(fmaf(r0.x, sc, bi), 0.0f);
        const float v1 = fmaxf(fmaf(r0.y, sc, bi), 0.0f);
        const float v2 = fmaxf(fmaf(r0.z, sc, bi), 0.0f);
        const float v3 = fmaxf(fmaf(r0.w, sc, bi), 0.0f);
        const float u0 = fmaxf(fmaf(r1.x, sc, bi), 0.0f);
        const float u1 = fmaxf(fmaf(r1.y, sc, bi), 0.0f);
        const float u2 = fmaxf(fmaf(r1.z, sc, bi), 0.0f);
        const float u3 = fmaxf(fmaf(r1.w, sc, bi), 0.0f);

        // 2x2 pool sums (the *0.25 is folded into the weights)
        const float p0 = (v0 + v1) + (u0 + u1);
        const float p1 = (v2 + v3) + (u2 + u3);
        const unsigned long long p = pack_f32x2(p0, p1);

        // Channel GEMM accumulate, packed over the two pixels
        const unsigned long long* w2 =
            reinterpret_cast<const unsigned long long*>(&s_w2[c * C_OUT]);
#pragma unroll
        for (int d = 0; d < C_OUT; d++) {
            fma_f32x2(acc[d], p, w2[d]);
        }
    }

    // Output: out[n][d][h2][2*wq .. 2*wq+1]; acc bits are exactly {p0,p1} floats
    float2* o = reinterpret_cast<float2*>(
        out + (size_t)n * C_OUT * (POUT * POUT) + h2 * POUT + 2 * wq);
#pragma unroll
    for (int d = 0; d < C_OUT; d++) {
        o[(size_t)d * (POUT * POUT / 2)] =
            *reinterpret_cast<const float2*>(&acc[d]);
    }
}

extern "C" void kernel_launch(void* const* d_in, const int* in_sizes, int n_in,
                              void* d_out, int out_size)
{
    const float* x     = (const float*)d_in[0];
    const float* wmat  = (const float*)d_in[1];
    const float* scale = (const float*)d_in[2];
    const float* bias  = (const float*)d_in[3];
    float* out         = (float*)d_out;

    // 32 images * 128 pooled rows * 64 column-pairs = 262144 threads
    fused_bn_relu_pool_conv<<<1024, 256>>>(x, wmat, scale, bias, out);
}